// round 14
// baseline (speedup 1.0000x reference)
#include <cuda_runtime.h>
#include <cuda_fp16.h>
#include <cstdint>

// Problem constants
#define SEQ   4096
#define EMB   2048
#define NH    16
#define NKV   4
#define DHEAD 128
#define QKVD  3072   // packed q|k|v projection dim: 2048 + 512 + 512

// ---------------------------------------------------------------------------
// Scratch (device globals — no cudaMalloc allowed)
// ---------------------------------------------------------------------------
__device__ __half g_xh[SEQ * EMB];          // x fp16
__device__ __half g_wqkv[QKVD * EMB];       // packed [Wq;Wk;Wv] fp16 [3072,2048]
__device__ __half g_wo[EMB * EMB];          // Wo fp16
__device__ __half g_qkv[SEQ * QKVD];        // packed Q|K|V [4096,3072]
__device__ __half g_ao[SEQ * EMB];          // attention out (merged heads)

// ---------------------------------------------------------------------------
// Helpers
// ---------------------------------------------------------------------------
__device__ __forceinline__ unsigned smem_u32(const void* p) {
    return (unsigned)__cvta_generic_to_shared(p);
}

__device__ __forceinline__ void cp_async16(void* smem, const void* gmem) {
    asm volatile("cp.async.cg.shared.global [%0], [%1], 16;\n"
                 :: "r"(smem_u32(smem)), "l"(gmem));
}
__device__ __forceinline__ void cp_commit() {
    asm volatile("cp.async.commit_group;\n");
}
template <int N>
__device__ __forceinline__ void cp_wait() {
    asm volatile("cp.async.wait_group %0;\n" :: "n"(N));
}

__device__ __forceinline__ void ldm_x4(unsigned& r0, unsigned& r1,
                                       unsigned& r2, unsigned& r3, unsigned addr) {
    asm volatile("ldmatrix.sync.aligned.m8n8.x4.shared.b16 {%0,%1,%2,%3}, [%4];"
                 : "=r"(r0), "=r"(r1), "=r"(r2), "=r"(r3) : "r"(addr));
}
__device__ __forceinline__ void ldm_x4_t(unsigned& r0, unsigned& r1,
                                         unsigned& r2, unsigned& r3, unsigned addr) {
    asm volatile("ldmatrix.sync.aligned.m8n8.x4.trans.shared.b16 {%0,%1,%2,%3}, [%4];"
                 : "=r"(r0), "=r"(r1), "=r"(r2), "=r"(r3) : "r"(addr));
}

// f32-accumulate mma (2-pass HMMA)
__device__ __forceinline__ void mma16816(float* c, const unsigned* a,
                                         unsigned b0, unsigned b1) {
    asm volatile(
        "mma.sync.aligned.m16n8k16.row.col.f32.f16.f16.f32 "
        "{%0,%1,%2,%3}, {%4,%5,%6,%7}, {%8,%9}, {%0,%1,%2,%3};"
        : "+f"(c[0]), "+f"(c[1]), "+f"(c[2]), "+f"(c[3])
        : "r"(a[0]), "r"(a[1]), "r"(a[2]), "r"(a[3]), "r"(b0), "r"(b1));
}

// f16-accumulate mma (1-pass HMMA). C fragment: 2 b32 regs = 4 halfs,
// reg0 = (row g, cols 2t..2t+1), reg1 = (row g+8, cols 2t..2t+1).
__device__ __forceinline__ void mma16816_h(unsigned* c, const unsigned* a,
                                           unsigned b0, unsigned b1) {
    asm volatile(
        "mma.sync.aligned.m16n8k16.row.col.f16.f16.f16.f16 "
        "{%0,%1}, {%2,%3,%4,%5}, {%6,%7}, {%0,%1};"
        : "+r"(c[0]), "+r"(c[1])
        : "r"(a[0]), "r"(a[1]), "r"(a[2]), "r"(a[3]), "r"(b0), "r"(b1));
}

// ---------------------------------------------------------------------------
// fp32 -> fp16 convert (vectorized, n divisible by 4)
// ---------------------------------------------------------------------------
__global__ void cvt_f32_f16(const float* __restrict__ in, __half* __restrict__ out, int n) {
    int idx = (blockIdx.x * blockDim.x + threadIdx.x) * 4;
    if (idx < n) {
        float4 v = *reinterpret_cast<const float4*>(in + idx);
        __half2* o = reinterpret_cast<__half2*>(out + idx);
        o[0] = __floats2half2_rn(v.x, v.y);
        o[1] = __floats2half2_rn(v.z, v.w);
    }
}

// ---------------------------------------------------------------------------
// NT GEMM: C[M,N] = A[M,K] @ B[N,K]^T, fp16 in.
// Inner accumulate in f16 (1-pass HMMA), promoted to f32 registers every
// BK=32 k-chunk (partial sums span only 32 terms -> fp16-safe).
// BM=128, BN=128, BK=32, 256 threads (8 warps: 4 in M x 2 in N).
// 4-stage cp.async pipeline, one __syncthreads per k-iteration.
// SMEM stride 40 halfs (conflict-free ldmatrix). Dynamic smem = 81920 B.
// ---------------------------------------------------------------------------
#define GSTG 5120   // 128*40 halfs per stage

template <bool OUT_HALF>
__global__ __launch_bounds__(256) void gemm_nt_f16(
    const __half* __restrict__ A, const __half* __restrict__ B,
    void* __restrict__ Cp, int M, int N, int K)
{
    extern __shared__ __half gsm[];
    __half* As = gsm;               // 4 stages
    __half* Bs = gsm + 4 * GSTG;    // 4 stages

    const int tid = threadIdx.x;
    const int lane = tid & 31, wid = tid >> 5;
    const int wm = wid & 3, wn = wid >> 2;          // warp tile 32 x 64
    const int m0 = blockIdx.y * 128, n0 = blockIdx.x * 128;
    const int lr = lane & 7, sel = lane >> 3;

    const int nk = K >> 5;

    auto issue = [&](int it) {
        int s = it & 3;
        __half* as = As + s * GSTG;
        __half* bs = Bs + s * GSTG;
        int k0 = it * 32;
#pragma unroll
        for (int i = 0; i < 2; i++) {
            int v = tid + i * 256;
            int row = v >> 2, col = (v & 3) * 8;
            cp_async16(&as[row * 40 + col], A + (size_t)(m0 + row) * K + k0 + col);
            cp_async16(&bs[row * 40 + col], B + (size_t)(n0 + row) * K + k0 + col);
        }
    };

    float acc[2][8][4];
#pragma unroll
    for (int mt = 0; mt < 2; mt++)
#pragma unroll
        for (int nt = 0; nt < 8; nt++)
#pragma unroll
            for (int j = 0; j < 4; j++) acc[mt][nt][j] = 0.f;

    issue(0); cp_commit();
    issue(1); cp_commit();
    issue(2); cp_commit();

    for (int i = 0; i < nk; i++) {
        cp_wait<2>();
        __syncthreads();
        if (i + 3 < nk) issue(i + 3);
        cp_commit();

        int s = i & 3;
        const __half* as = As + s * GSTG;
        const __half* bs = Bs + s * GSTG;

        // f16 chunk accumulators (zeroed per 32-k chunk)
        unsigned hacc[2][8][2];
#pragma unroll
        for (int mt = 0; mt < 2; mt++)
#pragma unroll
            for (int nt = 0; nt < 8; nt++) {
                hacc[mt][nt][0] = 0u; hacc[mt][nt][1] = 0u;
            }

#pragma unroll
        for (int ks = 0; ks < 32; ks += 16) {
            unsigned a[2][4];
#pragma unroll
            for (int mt = 0; mt < 2; mt++) {
                int row = wm * 32 + mt * 16 + lr + (sel & 1) * 8;
                int col = ks + (sel >> 1) * 8;
                ldm_x4(a[mt][0], a[mt][1], a[mt][2], a[mt][3],
                       smem_u32(&as[row * 40 + col]));
            }
#pragma unroll
            for (int np = 0; np < 4; np++) {
                unsigned b[4];
                int row = wn * 64 + np * 16 + lr + (sel >> 1) * 8;
                int col = ks + (sel & 1) * 8;
                ldm_x4(b[0], b[1], b[2], b[3], smem_u32(&bs[row * 40 + col]));
#pragma unroll
                for (int mt = 0; mt < 2; mt++) {
                    mma16816_h(hacc[mt][2 * np],     a[mt], b[0], b[1]);
                    mma16816_h(hacc[mt][2 * np + 1], a[mt], b[2], b[3]);
                }
            }
        }

        // promote chunk -> f32
#pragma unroll
        for (int mt = 0; mt < 2; mt++)
#pragma unroll
            for (int nt = 0; nt < 8; nt++) {
                float2 f0 = __half22float2(*reinterpret_cast<__half2*>(&hacc[mt][nt][0]));
                float2 f1 = __half22float2(*reinterpret_cast<__half2*>(&hacc[mt][nt][1]));
                acc[mt][nt][0] += f0.x; acc[mt][nt][1] += f0.y;
                acc[mt][nt][2] += f1.x; acc[mt][nt][3] += f1.y;
            }
    }

    const int g = lane >> 2, t = lane & 3;
#pragma unroll
    for (int mt = 0; mt < 2; mt++) {
#pragma unroll
        for (int nt = 0; nt < 8; nt++) {
            int row = m0 + wm * 32 + mt * 16 + g;
            int col = n0 + wn * 64 + nt * 8 + t * 2;
            if (OUT_HALF) {
                __half* C = (__half*)Cp;
                *reinterpret_cast<__half2*>(C + (size_t)row * N + col) =
                    __floats2half2_rn(acc[mt][nt][0], acc[mt][nt][1]);
                *reinterpret_cast<__half2*>(C + (size_t)(row + 8) * N + col) =
                    __floats2half2_rn(acc[mt][nt][2], acc[mt][nt][3]);
            } else {
                float* C = (float*)Cp;
                *reinterpret_cast<float2*>(C + (size_t)row * N + col) =
                    make_float2(acc[mt][nt][0], acc[mt][nt][1]);
                *reinterpret_cast<float2*>(C + (size_t)(row + 8) * N + col) =
                    make_float2(acc[mt][nt][2], acc[mt][nt][3]);
            }
        }
    }
}

// ---------------------------------------------------------------------------
// Flash attention, non-causal. grid = (SEQ/128, NH), 256 threads (8 warps).
// Each warp owns 16 q-rows (row stats in lane quads). KV tiled by 64.
// QK^T: f32-accumulate (feeds exp — tightest error path).
// P@V:  f16-accumulate per tile (1-pass HMMA), promoted into the f32 O
//       accumulator with the alpha rescale folded in.
// 3-stage cp.async KV pipeline. Reads packed QKV [4096,3072].
// Dynamic smem = (128 + 3*128) * 136 * 2 = 139264 B.
// ---------------------------------------------------------------------------
#define FSTG (128 * 136)  // one KV stage (K 64x136 + V 64x136) in halfs

__global__ __launch_bounds__(256) void flash_attn(
    const __half* __restrict__ QKV, __half* __restrict__ O)
{
    extern __shared__ __half fsm[];
    __half* Qs  = fsm;            // 128*136
    __half* KVs = fsm + FSTG;     // 3 stages

    const int tid = threadIdx.x, lane = tid & 31, wid = tid >> 5;
    const int h = blockIdx.y;
    const int q0 = blockIdx.x * 128;
    const int kvh = h >> 2;                         // GQA repeat_interleave(4)
    const int lr = lane & 7, sel = lane >> 3;
    const int g = lane >> 2, t = lane & 3;

    const __half* qg = QKV + (size_t)q0 * QKVD + h * DHEAD;
    const __half* kg = QKV + 2048 + (size_t)kvh * DHEAD;
    const __half* vg = QKV + 2560 + (size_t)kvh * DHEAD;

    auto issueKV = [&](int it) {
        int s = it % 3;
        __half* ks = KVs + s * FSTG;
        __half* vs = ks + 64 * 136;
        int kv0 = it * 64;
#pragma unroll
        for (int i = 0; i < 4; i++) {
            int v = tid + i * 256;
            int row = v >> 4, col = (v & 15) * 8;
            cp_async16(&ks[row * 136 + col], kg + (size_t)(kv0 + row) * QKVD + col);
            cp_async16(&vs[row * 136 + col], vg + (size_t)(kv0 + row) * QKVD + col);
        }
    };

    // group 0: Q tile
#pragma unroll
    for (int i = 0; i < 8; i++) {
        int v = tid + i * 256;
        int row = v >> 4, col = (v & 15) * 8;
        cp_async16(&Qs[row * 136 + col], qg + (size_t)row * QKVD + col);
    }
    cp_commit();
    issueKV(0); cp_commit();   // group 1
    issueKV(1); cp_commit();   // group 2

    cp_wait<2>();              // Q ready
    __syncthreads();

    unsigned qf[8][4];
    {
        int row = wid * 16 + lr + (sel & 1) * 8;
#pragma unroll
        for (int kt = 0; kt < 8; kt++) {
            int col = kt * 16 + (sel >> 1) * 8;
            ldm_x4(qf[kt][0], qf[kt][1], qf[kt][2], qf[kt][3],
                   smem_u32(&Qs[row * 136 + col]));
        }
    }

    float oacc[16][4];
#pragma unroll
    for (int nt = 0; nt < 16; nt++)
#pragma unroll
        for (int j = 0; j < 4; j++) oacc[nt][j] = 0.f;

    float mrow0 = -1e30f, mrow1 = -1e30f;
    float lrow0 = 0.f, lrow1 = 0.f;
    // (1/sqrt(128)) * log2(e): exp -> exp2
    const float scale = 0.1275174302f;

    const int nkv = SEQ / 64;
    for (int i = 0; i < nkv; i++) {
        cp_wait<1>();          // KV tile i ready
        __syncthreads();
        if (i + 2 < nkv) issueKV(i + 2);
        cp_commit();

        int s = i % 3;
        const __half* Ks = KVs + s * FSTG;
        const __half* Vs = Ks + 64 * 136;

        // --- S = Q @ K^T  (16 x 64 per warp), f32 accumulate ---
        float sacc[8][4];
#pragma unroll
        for (int nt = 0; nt < 8; nt++)
#pragma unroll
            for (int j = 0; j < 4; j++) sacc[nt][j] = 0.f;

#pragma unroll
        for (int kt = 0; kt < 8; kt++) {
#pragma unroll
            for (int np = 0; np < 4; np++) {
                unsigned b[4];
                int row = np * 16 + lr + (sel >> 1) * 8;
                int col = kt * 16 + (sel & 1) * 8;
                ldm_x4(b[0], b[1], b[2], b[3], smem_u32(&Ks[row * 136 + col]));
                mma16816(sacc[2 * np], qf[kt], b[0], b[1]);
                mma16816(sacc[2 * np + 1], qf[kt], b[2], b[3]);
            }
        }

        // --- online softmax (base-2 domain) ---
        float mnew0 = mrow0, mnew1 = mrow1;
#pragma unroll
        for (int nt = 0; nt < 8; nt++) {
#pragma unroll
            for (int j = 0; j < 4; j++) sacc[nt][j] *= scale;
            mnew0 = fmaxf(mnew0, fmaxf(sacc[nt][0], sacc[nt][1]));
            mnew1 = fmaxf(mnew1, fmaxf(sacc[nt][2], sacc[nt][3]));
        }
        mnew0 = fmaxf(mnew0, __shfl_xor_sync(0xffffffffu, mnew0, 1));
        mnew0 = fmaxf(mnew0, __shfl_xor_sync(0xffffffffu, mnew0, 2));
        mnew1 = fmaxf(mnew1, __shfl_xor_sync(0xffffffffu, mnew1, 1));
        mnew1 = fmaxf(mnew1, __shfl_xor_sync(0xffffffffu, mnew1, 2));

        float alpha0 = exp2f(mrow0 - mnew0);
        float alpha1 = exp2f(mrow1 - mnew1);
        float rsum0 = 0.f, rsum1 = 0.f;

        unsigned ph[4][4];
#pragma unroll
        for (int nt = 0; nt < 8; nt++) {
            float p0 = exp2f(sacc[nt][0] - mnew0);
            float p1 = exp2f(sacc[nt][1] - mnew0);
            float p2 = exp2f(sacc[nt][2] - mnew1);
            float p3 = exp2f(sacc[nt][3] - mnew1);
            rsum0 += p0 + p1;
            rsum1 += p2 + p3;
            __half2 h01 = __floats2half2_rn(p0, p1);
            __half2 h23 = __floats2half2_rn(p2, p3);
            int kt = nt >> 1;
            if ((nt & 1) == 0) {
                ph[kt][0] = *reinterpret_cast<unsigned*>(&h01);
                ph[kt][1] = *reinterpret_cast<unsigned*>(&h23);
            } else {
                ph[kt][2] = *reinterpret_cast<unsigned*>(&h01);
                ph[kt][3] = *reinterpret_cast<unsigned*>(&h23);
            }
        }
        rsum0 += __shfl_xor_sync(0xffffffffu, rsum0, 1);
        rsum0 += __shfl_xor_sync(0xffffffffu, rsum0, 2);
        rsum1 += __shfl_xor_sync(0xffffffffu, rsum1, 1);
        rsum1 += __shfl_xor_sync(0xffffffffu, rsum1, 2);

        lrow0 = lrow0 * alpha0 + rsum0;
        lrow1 = lrow1 * alpha1 + rsum1;
        mrow0 = mnew0;
        mrow1 = mnew1;

        // --- O_tile = P @ V in f16 accumulate (1-pass HMMA) ---
        unsigned ohf[16][2];
#pragma unroll
        for (int nt = 0; nt < 16; nt++) { ohf[nt][0] = 0u; ohf[nt][1] = 0u; }

#pragma unroll
        for (int kt = 0; kt < 4; kt++) {
#pragma unroll
            for (int np = 0; np < 8; np++) {
                unsigned b[4];
                int row = kt * 16 + lr + (sel & 1) * 8;
                int col = np * 16 + (sel >> 1) * 8;
                ldm_x4_t(b[0], b[1], b[2], b[3], smem_u32(&Vs[row * 136 + col]));
                mma16816_h(ohf[2 * np],     ph[kt], b[0], b[1]);
                mma16816_h(ohf[2 * np + 1], ph[kt], b[2], b[3]);
            }
        }

        // promote + fold alpha rescale: O = O*alpha + tile
#pragma unroll
        for (int nt = 0; nt < 16; nt++) {
            float2 f0 = __half22float2(*reinterpret_cast<__half2*>(&ohf[nt][0]));
            float2 f1 = __half22float2(*reinterpret_cast<__half2*>(&ohf[nt][1]));
            oacc[nt][0] = oacc[nt][0] * alpha0 + f0.x;
            oacc[nt][1] = oacc[nt][1] * alpha0 + f0.y;
            oacc[nt][2] = oacc[nt][2] * alpha1 + f1.x;
            oacc[nt][3] = oacc[nt][3] * alpha1 + f1.y;
        }
    }

    // --- epilogue: O / l, cast fp16, store merged-head layout [s, h*D+d] ---
    float inv0 = 1.f / lrow0;
    float inv1 = 1.f / lrow1;
    __half* og = O + (size_t)(q0 + wid * 16) * EMB + h * DHEAD;
#pragma unroll
    for (int nt = 0; nt < 16; nt++) {
        int col = nt * 8 + t * 2;
        *reinterpret_cast<__half2*>(og + (size_t)g * EMB + col) =
            __floats2half2_rn(oacc[nt][0] * inv0, oacc[nt][1] * inv0);
        *reinterpret_cast<__half2*>(og + (size_t)(g + 8) * EMB + col) =
            __floats2half2_rn(oacc[nt][2] * inv1, oacc[nt][3] * inv1);
    }
}

// ---------------------------------------------------------------------------
// kernel_launch
// ---------------------------------------------------------------------------
extern "C" void kernel_launch(void* const* d_in, const int* in_sizes, int n_in,
                              void* d_out, int out_size) {
    (void)in_sizes; (void)n_in; (void)out_size;
    const float* x  = (const float*)d_in[0];
    const float* Wq = (const float*)d_in[1];
    const float* Wk = (const float*)d_in[2];
    const float* Wv = (const float*)d_in[3];
    const float* Wo = (const float*)d_in[4];

    void *xh, *wqkv, *wo, *qkv, *ao;
    cudaGetSymbolAddress(&xh,   g_xh);
    cudaGetSymbolAddress(&wqkv, g_wqkv);
    cudaGetSymbolAddress(&wo,   g_wo);
    cudaGetSymbolAddress(&qkv,  g_qkv);
    cudaGetSymbolAddress(&ao,   g_ao);

    const int gemm_smem  = 2 * 4 * GSTG * (int)sizeof(__half);   // 81920
    const int flash_smem = 4 * FSTG * (int)sizeof(__half);       // 139264
    cudaFuncSetAttribute(gemm_nt_f16<true>,
                         cudaFuncAttributeMaxDynamicSharedMemorySize, gemm_smem);
    cudaFuncSetAttribute(gemm_nt_f16<false>,
                         cudaFuncAttributeMaxDynamicSharedMemorySize, gemm_smem);
    cudaFuncSetAttribute(flash_attn,
                         cudaFuncAttributeMaxDynamicSharedMemorySize, flash_smem);

    // fp32 -> fp16 converts (Wq/Wk/Wv packed into one weight buffer)
    cvt_f32_f16<<<(SEQ * EMB) / 1024, 256>>>(x, (__half*)xh, SEQ * EMB);
    cvt_f32_f16<<<(EMB * EMB) / 1024, 256>>>(Wq, (__half*)wqkv, EMB * EMB);
    cvt_f32_f16<<<(512 * EMB) / 1024, 256>>>(Wk, (__half*)wqkv + 2048 * 2048, 512 * EMB);
    cvt_f32_f16<<<(512 * EMB) / 1024, 256>>>(Wv, (__half*)wqkv + 2560 * 2048, 512 * EMB);
    cvt_f32_f16<<<(EMB * EMB) / 1024, 256>>>(Wo, (__half*)wo, EMB * EMB);

    // fused QKV projection: [4096,3072] = X @ [Wq;Wk;Wv]^T
    gemm_nt_f16<true><<<dim3(QKVD / 128, SEQ / 128), 256, gemm_smem>>>(
        (const __half*)xh, (const __half*)wqkv, qkv, SEQ, QKVD, EMB);

    // attention
    flash_attn<<<dim3(SEQ / 128, NH), 256, flash_smem>>>(
        (const __half*)qkv, (__half*)ao);

    // output projection (fp32 out)
    gemm_nt_f16<false><<<dim3(EMB / 128, SEQ / 128), 256, gemm_smem>>>(
        (const __half*)ao, (const __half*)wo, d_out, SEQ, EMB, EMB);
}

// round 15
// speedup vs baseline: 1.1804x; 1.1804x over previous
#include <cuda_runtime.h>
#include <cuda_fp16.h>
#include <cstdint>

// Problem constants
#define SEQ   4096
#define EMB   2048
#define NH    16
#define NKV   4
#define DHEAD 128
#define QKVD  3072   // packed q|k|v projection dim: 2048 + 512 + 512
#define NSPLIT 2     // split-KV factor in flash attention

// ---------------------------------------------------------------------------
// Scratch (device globals — no cudaMalloc allowed)
// ---------------------------------------------------------------------------
__device__ __half g_xh[SEQ * EMB];            // x fp16
__device__ __half g_wqkv[QKVD * EMB];         // packed [Wq;Wk;Wv] fp16
__device__ __half g_wo[EMB * EMB];            // Wo fp16
__device__ __half g_qkv[SEQ * QKVD];          // packed Q|K|V [4096,3072]
__device__ __half g_ao[SEQ * EMB];            // attention out (merged heads)
__device__ float  g_po[NSPLIT * NH * SEQ * DHEAD];  // unnormalized O partials (67MB)
__device__ float  g_ml[NSPLIT * NH * SEQ * 2];      // (m, l) per row per split

// ---------------------------------------------------------------------------
// Helpers
// ---------------------------------------------------------------------------
__device__ __forceinline__ unsigned smem_u32(const void* p) {
    return (unsigned)__cvta_generic_to_shared(p);
}

__device__ __forceinline__ void cp_async16(void* smem, const void* gmem) {
    asm volatile("cp.async.cg.shared.global [%0], [%1], 16;\n"
                 :: "r"(smem_u32(smem)), "l"(gmem));
}
__device__ __forceinline__ void cp_commit() {
    asm volatile("cp.async.commit_group;\n");
}
template <int N>
__device__ __forceinline__ void cp_wait() {
    asm volatile("cp.async.wait_group %0;\n" :: "n"(N));
}

__device__ __forceinline__ void ldm_x4(unsigned& r0, unsigned& r1,
                                       unsigned& r2, unsigned& r3, unsigned addr) {
    asm volatile("ldmatrix.sync.aligned.m8n8.x4.shared.b16 {%0,%1,%2,%3}, [%4];"
                 : "=r"(r0), "=r"(r1), "=r"(r2), "=r"(r3) : "r"(addr));
}
__device__ __forceinline__ void ldm_x4_t(unsigned& r0, unsigned& r1,
                                         unsigned& r2, unsigned& r3, unsigned addr) {
    asm volatile("ldmatrix.sync.aligned.m8n8.x4.trans.shared.b16 {%0,%1,%2,%3}, [%4];"
                 : "=r"(r0), "=r"(r1), "=r"(r2), "=r"(r3) : "r"(addr));
}
__device__ __forceinline__ void mma16816(float* c, const unsigned* a,
                                         unsigned b0, unsigned b1) {
    asm volatile(
        "mma.sync.aligned.m16n8k16.row.col.f32.f16.f16.f32 "
        "{%0,%1,%2,%3}, {%4,%5,%6,%7}, {%8,%9}, {%0,%1,%2,%3};"
        : "+f"(c[0]), "+f"(c[1]), "+f"(c[2]), "+f"(c[3])
        : "r"(a[0]), "r"(a[1]), "r"(a[2]), "r"(a[3]), "r"(b0), "r"(b1));
}

// ---------------------------------------------------------------------------
// Fused fp32 -> fp16 convert for all five inputs (one launch).
// Region table in float4 units:
//   x   : [0,        2097152)  -> g_xh
//   Wq  : [2097152,  3145728)  -> g_wqkv + 0
//   Wk  : [3145728,  3407872)  -> g_wqkv + 4194304
//   Wv  : [3407872,  3670016)  -> g_wqkv + 5242880
//   Wo  : [3670016,  4718592)  -> g_wo
// ---------------------------------------------------------------------------
__global__ void cvt_all(const float* __restrict__ x,  const float* __restrict__ wq,
                        const float* __restrict__ wk, const float* __restrict__ wv,
                        const float* __restrict__ wo,
                        __half* __restrict__ xh, __half* __restrict__ wqkv,
                        __half* __restrict__ woh)
{
    int u = blockIdx.x * blockDim.x + threadIdx.x;
    const float* src; __half* dst; int off;
    if (u < 2097152)       { src = x;  dst = xh;             off = u; }
    else if (u < 3145728)  { src = wq; dst = wqkv;           off = u - 2097152; }
    else if (u < 3407872)  { src = wk; dst = wqkv + 4194304; off = u - 3145728; }
    else if (u < 3670016)  { src = wv; dst = wqkv + 5242880; off = u - 3407872; }
    else                   { src = wo; dst = woh;            off = u - 3670016; }
    float4 v = reinterpret_cast<const float4*>(src)[off];
    __half2* o = reinterpret_cast<__half2*>(dst + (size_t)off * 4);
    o[0] = __floats2half2_rn(v.x, v.y);
    o[1] = __floats2half2_rn(v.z, v.w);
}

// ---------------------------------------------------------------------------
// NT GEMM: C[M,N] = A[M,K] @ B[N,K]^T, fp16 in, fp32 accumulate.
// BM=128, BN=128, BK=32, 256 threads (8 warps: 4 in M x 2 in N).
// 4-stage cp.async pipeline, one __syncthreads per k-iteration.
// SMEM stride 40 halfs. Dynamic smem = 81920 B.
// ---------------------------------------------------------------------------
#define GSTG 5120   // 128*40 halfs per stage

template <bool OUT_HALF>
__global__ __launch_bounds__(256, 2) void gemm_nt_f16(
    const __half* __restrict__ A, const __half* __restrict__ B,
    void* __restrict__ Cp, int M, int N, int K)
{
    extern __shared__ __half gsm[];
    __half* As = gsm;
    __half* Bs = gsm + 4 * GSTG;

    const int tid = threadIdx.x;
    const int lane = tid & 31, wid = tid >> 5;
    const int wm = wid & 3, wn = wid >> 2;
    const int m0 = blockIdx.y * 128, n0 = blockIdx.x * 128;
    const int lr = lane & 7, sel = lane >> 3;

    const int nk = K >> 5;

    auto issue = [&](int it) {
        int s = it & 3;
        __half* as = As + s * GSTG;
        __half* bs = Bs + s * GSTG;
        int k0 = it * 32;
#pragma unroll
        for (int i = 0; i < 2; i++) {
            int v = tid + i * 256;
            int row = v >> 2, col = (v & 3) * 8;
            cp_async16(&as[row * 40 + col], A + (size_t)(m0 + row) * K + k0 + col);
            cp_async16(&bs[row * 40 + col], B + (size_t)(n0 + row) * K + k0 + col);
        }
    };

    float acc[2][8][4];
#pragma unroll
    for (int mt = 0; mt < 2; mt++)
#pragma unroll
        for (int nt = 0; nt < 8; nt++)
#pragma unroll
            for (int j = 0; j < 4; j++) acc[mt][nt][j] = 0.f;

    issue(0); cp_commit();
    issue(1); cp_commit();
    issue(2); cp_commit();

    for (int i = 0; i < nk; i++) {
        cp_wait<2>();
        __syncthreads();
        if (i + 3 < nk) issue(i + 3);
        cp_commit();

        int s = i & 3;
        const __half* as = As + s * GSTG;
        const __half* bs = Bs + s * GSTG;

#pragma unroll
        for (int ks = 0; ks < 32; ks += 16) {
            unsigned a[2][4];
#pragma unroll
            for (int mt = 0; mt < 2; mt++) {
                int row = wm * 32 + mt * 16 + lr + (sel & 1) * 8;
                int col = ks + (sel >> 1) * 8;
                ldm_x4(a[mt][0], a[mt][1], a[mt][2], a[mt][3],
                       smem_u32(&as[row * 40 + col]));
            }
#pragma unroll
            for (int np = 0; np < 4; np++) {
                unsigned b[4];
                int row = wn * 64 + np * 16 + lr + (sel >> 1) * 8;
                int col = ks + (sel & 1) * 8;
                ldm_x4(b[0], b[1], b[2], b[3], smem_u32(&bs[row * 40 + col]));
#pragma unroll
                for (int mt = 0; mt < 2; mt++) {
                    mma16816(acc[mt][2 * np], a[mt], b[0], b[1]);
                    mma16816(acc[mt][2 * np + 1], a[mt], b[2], b[3]);
                }
            }
        }
    }

    const int g = lane >> 2, t = lane & 3;
#pragma unroll
    for (int mt = 0; mt < 2; mt++) {
#pragma unroll
        for (int nt = 0; nt < 8; nt++) {
            int row = m0 + wm * 32 + mt * 16 + g;
            int col = n0 + wn * 64 + nt * 8 + t * 2;
            if (OUT_HALF) {
                __half* C = (__half*)Cp;
                *reinterpret_cast<__half2*>(C + (size_t)row * N + col) =
                    __floats2half2_rn(acc[mt][nt][0], acc[mt][nt][1]);
                *reinterpret_cast<__half2*>(C + (size_t)(row + 8) * N + col) =
                    __floats2half2_rn(acc[mt][nt][2], acc[mt][nt][3]);
            } else {
                float* C = (float*)Cp;
                *reinterpret_cast<float2*>(C + (size_t)row * N + col) =
                    make_float2(acc[mt][nt][0], acc[mt][nt][1]);
                *reinterpret_cast<float2*>(C + (size_t)(row + 8) * N + col) =
                    make_float2(acc[mt][nt][2], acc[mt][nt][3]);
            }
        }
    }
}

// ---------------------------------------------------------------------------
// Flash attention with split-KV. grid = (SEQ/128, NH, NSPLIT), 256 threads.
// Each CTA: 128 q-rows of one head over HALF the KV range (independent online
// softmax); writes unnormalized fp32 O-partial + (m, l). A combine kernel
// merges the two splits. Grid = 1024 CTAs -> wave tail ~1% (vs 15% at 512).
// Dynamic smem = (128 + 3*128) * 136 * 2 = 139264 B.
// ---------------------------------------------------------------------------
#define FSTG (128 * 136)  // one KV stage (K 64x136 + V 64x136) in halfs
#define KVHALF (SEQ / NSPLIT)

__global__ __launch_bounds__(256) void flash_attn(
    const __half* __restrict__ QKV, float* __restrict__ PO, float* __restrict__ ML)
{
    extern __shared__ __half fsm[];
    __half* Qs  = fsm;            // 128*136
    __half* KVs = fsm + FSTG;     // 3 stages

    const int tid = threadIdx.x, lane = tid & 31, wid = tid >> 5;
    const int h = blockIdx.y;
    const int q0 = blockIdx.x * 128;
    const int sp = blockIdx.z;                      // KV split index
    const int kvh = h >> 2;                         // GQA repeat_interleave(4)
    const int lr = lane & 7, sel = lane >> 3;
    const int g = lane >> 2, t = lane & 3;

    const __half* qg = QKV + (size_t)q0 * QKVD + h * DHEAD;
    const __half* kg = QKV + 2048 + (size_t)kvh * DHEAD + (size_t)sp * KVHALF * QKVD;
    const __half* vg = QKV + 2560 + (size_t)kvh * DHEAD + (size_t)sp * KVHALF * QKVD;

    auto issueKV = [&](int it) {
        int s = it % 3;
        __half* ks = KVs + s * FSTG;
        __half* vs = ks + 64 * 136;
        int kv0 = it * 64;
#pragma unroll
        for (int i = 0; i < 4; i++) {
            int v = tid + i * 256;
            int row = v >> 4, col = (v & 15) * 8;
            cp_async16(&ks[row * 136 + col], kg + (size_t)(kv0 + row) * QKVD + col);
            cp_async16(&vs[row * 136 + col], vg + (size_t)(kv0 + row) * QKVD + col);
        }
    };

    // group 0: Q tile
#pragma unroll
    for (int i = 0; i < 8; i++) {
        int v = tid + i * 256;
        int row = v >> 4, col = (v & 15) * 8;
        cp_async16(&Qs[row * 136 + col], qg + (size_t)row * QKVD + col);
    }
    cp_commit();
    issueKV(0); cp_commit();
    issueKV(1); cp_commit();

    cp_wait<2>();
    __syncthreads();

    unsigned qf[8][4];
    {
        int row = wid * 16 + lr + (sel & 1) * 8;
#pragma unroll
        for (int kt = 0; kt < 8; kt++) {
            int col = kt * 16 + (sel >> 1) * 8;
            ldm_x4(qf[kt][0], qf[kt][1], qf[kt][2], qf[kt][3],
                   smem_u32(&Qs[row * 136 + col]));
        }
    }

    float oacc[16][4];
#pragma unroll
    for (int nt = 0; nt < 16; nt++)
#pragma unroll
        for (int j = 0; j < 4; j++) oacc[nt][j] = 0.f;

    float mrow0 = -1e30f, mrow1 = -1e30f;
    float lrow0 = 0.f, lrow1 = 0.f;
    const float scale = 0.1275174302f;   // (1/sqrt(128)) * log2(e)

    const int nkv = KVHALF / 64;
    for (int i = 0; i < nkv; i++) {
        cp_wait<1>();
        __syncthreads();
        if (i + 2 < nkv) issueKV(i + 2);
        cp_commit();

        int s = i % 3;
        const __half* Ks = KVs + s * FSTG;
        const __half* Vs = Ks + 64 * 136;

        // --- S = Q @ K^T  (16 x 64 per warp) ---
        float sacc[8][4];
#pragma unroll
        for (int nt = 0; nt < 8; nt++)
#pragma unroll
            for (int j = 0; j < 4; j++) sacc[nt][j] = 0.f;

#pragma unroll
        for (int kt = 0; kt < 8; kt++) {
#pragma unroll
            for (int np = 0; np < 4; np++) {
                unsigned b[4];
                int row = np * 16 + lr + (sel >> 1) * 8;
                int col = kt * 16 + (sel & 1) * 8;
                ldm_x4(b[0], b[1], b[2], b[3], smem_u32(&Ks[row * 136 + col]));
                mma16816(sacc[2 * np], qf[kt], b[0], b[1]);
                mma16816(sacc[2 * np + 1], qf[kt], b[2], b[3]);
            }
        }

        // --- online softmax (base-2 domain) ---
        float mnew0 = mrow0, mnew1 = mrow1;
#pragma unroll
        for (int nt = 0; nt < 8; nt++) {
#pragma unroll
            for (int j = 0; j < 4; j++) sacc[nt][j] *= scale;
            mnew0 = fmaxf(mnew0, fmaxf(sacc[nt][0], sacc[nt][1]));
            mnew1 = fmaxf(mnew1, fmaxf(sacc[nt][2], sacc[nt][3]));
        }
        mnew0 = fmaxf(mnew0, __shfl_xor_sync(0xffffffffu, mnew0, 1));
        mnew0 = fmaxf(mnew0, __shfl_xor_sync(0xffffffffu, mnew0, 2));
        mnew1 = fmaxf(mnew1, __shfl_xor_sync(0xffffffffu, mnew1, 1));
        mnew1 = fmaxf(mnew1, __shfl_xor_sync(0xffffffffu, mnew1, 2));

        float alpha0 = exp2f(mrow0 - mnew0);
        float alpha1 = exp2f(mrow1 - mnew1);
        float rsum0 = 0.f, rsum1 = 0.f;

        unsigned ph[4][4];
#pragma unroll
        for (int nt = 0; nt < 8; nt++) {
            float p0 = exp2f(sacc[nt][0] - mnew0);
            float p1 = exp2f(sacc[nt][1] - mnew0);
            float p2 = exp2f(sacc[nt][2] - mnew1);
            float p3 = exp2f(sacc[nt][3] - mnew1);
            rsum0 += p0 + p1;
            rsum1 += p2 + p3;
            __half2 h01 = __floats2half2_rn(p0, p1);
            __half2 h23 = __floats2half2_rn(p2, p3);
            int kt = nt >> 1;
            if ((nt & 1) == 0) {
                ph[kt][0] = *reinterpret_cast<unsigned*>(&h01);
                ph[kt][1] = *reinterpret_cast<unsigned*>(&h23);
            } else {
                ph[kt][2] = *reinterpret_cast<unsigned*>(&h01);
                ph[kt][3] = *reinterpret_cast<unsigned*>(&h23);
            }
        }
        rsum0 += __shfl_xor_sync(0xffffffffu, rsum0, 1);
        rsum0 += __shfl_xor_sync(0xffffffffu, rsum0, 2);
        rsum1 += __shfl_xor_sync(0xffffffffu, rsum1, 1);
        rsum1 += __shfl_xor_sync(0xffffffffu, rsum1, 2);

        lrow0 = lrow0 * alpha0 + rsum0;
        lrow1 = lrow1 * alpha1 + rsum1;
        mrow0 = mnew0;
        mrow1 = mnew1;

#pragma unroll
        for (int nt = 0; nt < 16; nt++) {
            oacc[nt][0] *= alpha0; oacc[nt][1] *= alpha0;
            oacc[nt][2] *= alpha1; oacc[nt][3] *= alpha1;
        }

        // --- O += P @ V ---
#pragma unroll
        for (int kt = 0; kt < 4; kt++) {
#pragma unroll
            for (int np = 0; np < 8; np++) {
                unsigned b[4];
                int row = kt * 16 + lr + (sel & 1) * 8;
                int col = np * 16 + (sel >> 1) * 8;
                ldm_x4_t(b[0], b[1], b[2], b[3], smem_u32(&Vs[row * 136 + col]));
                mma16816(oacc[2 * np], ph[kt], b[0], b[1]);
                mma16816(oacc[2 * np + 1], ph[kt], b[2], b[3]);
            }
        }
    }

    // --- epilogue: store UNnormalized fp32 partials + (m, l) per row ---
    const size_t rowbase = ((size_t)(sp * NH + h) * SEQ + q0 + wid * 16);
    float* pg = PO + rowbase * DHEAD;
#pragma unroll
    for (int nt = 0; nt < 16; nt++) {
        int col = nt * 8 + t * 2;
        *reinterpret_cast<float2*>(pg + (size_t)g * DHEAD + col) =
            make_float2(oacc[nt][0], oacc[nt][1]);
        *reinterpret_cast<float2*>(pg + (size_t)(g + 8) * DHEAD + col) =
            make_float2(oacc[nt][2], oacc[nt][3]);
    }
    if (t == 0) {
        ML[(rowbase + g) * 2 + 0] = mrow0;
        ML[(rowbase + g) * 2 + 1] = lrow0;
        ML[(rowbase + g + 8) * 2 + 0] = mrow1;
        ML[(rowbase + g + 8) * 2 + 1] = lrow1;
    }
}

// ---------------------------------------------------------------------------
// Combine the NSPLIT=2 KV splits: O = (O0*w0 + O1*w1) / (l0*w0 + l1*w1),
// w_i = 2^(m_i - max(m)). Writes merged-head fp16 layout [s, h*D+d].
// threads = SEQ*NH*(DHEAD/4) = 2,097,152.
// ---------------------------------------------------------------------------
__global__ void combine_split(const float* __restrict__ po,
                              const float* __restrict__ ml,
                              __half* __restrict__ ao)
{
    int idx = blockIdx.x * blockDim.x + threadIdx.x;
    int d4 = idx & 31;
    int qh = idx >> 5;
    int h = qh & 15;
    int q = qh >> 4;

    size_t rb = (size_t)h * SEQ + q;
    const size_t SML = (size_t)NH * SEQ * 2;        // split stride in ml
    const size_t SPO = (size_t)NH * SEQ * DHEAD;    // split stride in po

    float m0 = ml[rb * 2 + 0], l0 = ml[rb * 2 + 1];
    float m1 = ml[SML + rb * 2 + 0], l1 = ml[SML + rb * 2 + 1];
    float mx = fmaxf(m0, m1);
    float w0 = exp2f(m0 - mx), w1 = exp2f(m1 - mx);
    float inv = 1.f / (l0 * w0 + l1 * w1);
    w0 *= inv; w1 *= inv;

    size_t pb = rb * DHEAD + d4 * 4;
    float4 a = *reinterpret_cast<const float4*>(po + pb);
    float4 b = *reinterpret_cast<const float4*>(po + SPO + pb);

    __half2* o = reinterpret_cast<__half2*>(ao + (size_t)q * EMB + h * DHEAD + d4 * 4);
    o[0] = __floats2half2_rn(a.x * w0 + b.x * w1, a.y * w0 + b.y * w1);
    o[1] = __floats2half2_rn(a.z * w0 + b.z * w1, a.w * w0 + b.w * w1);
}

// ---------------------------------------------------------------------------
// kernel_launch
// ---------------------------------------------------------------------------
extern "C" void kernel_launch(void* const* d_in, const int* in_sizes, int n_in,
                              void* d_out, int out_size) {
    (void)in_sizes; (void)n_in; (void)out_size;
    const float* x  = (const float*)d_in[0];
    const float* Wq = (const float*)d_in[1];
    const float* Wk = (const float*)d_in[2];
    const float* Wv = (const float*)d_in[3];
    const float* Wo = (const float*)d_in[4];

    void *xh, *wqkv, *wo, *qkv, *ao, *po, *ml;
    cudaGetSymbolAddress(&xh,   g_xh);
    cudaGetSymbolAddress(&wqkv, g_wqkv);
    cudaGetSymbolAddress(&wo,   g_wo);
    cudaGetSymbolAddress(&qkv,  g_qkv);
    cudaGetSymbolAddress(&ao,   g_ao);
    cudaGetSymbolAddress(&po,   g_po);
    cudaGetSymbolAddress(&ml,   g_ml);

    const int gemm_smem  = 2 * 4 * GSTG * (int)sizeof(__half);   // 81920
    const int flash_smem = 4 * FSTG * (int)sizeof(__half);       // 139264
    cudaFuncSetAttribute(gemm_nt_f16<true>,
                         cudaFuncAttributeMaxDynamicSharedMemorySize, gemm_smem);
    cudaFuncSetAttribute(gemm_nt_f16<false>,
                         cudaFuncAttributeMaxDynamicSharedMemorySize, gemm_smem);
    cudaFuncSetAttribute(flash_attn,
                         cudaFuncAttributeMaxDynamicSharedMemorySize, flash_smem);

    // fused fp32 -> fp16 converts (one launch)
    cvt_all<<<18432, 256>>>(x, Wq, Wk, Wv, Wo,
                            (__half*)xh, (__half*)wqkv, (__half*)wo);

    // fused QKV projection: [4096,3072] = X @ [Wq;Wk;Wv]^T
    gemm_nt_f16<true><<<dim3(QKVD / 128, SEQ / 128), 256, gemm_smem>>>(
        (const __half*)xh, (const __half*)wqkv, qkv, SEQ, QKVD, EMB);

    // attention (split-KV x2), then combine
    flash_attn<<<dim3(SEQ / 128, NH, NSPLIT), 256, flash_smem>>>(
        (const __half*)qkv, (float*)po, (float*)ml);
    combine_split<<<(SEQ * NH * (DHEAD / 4)) / 256, 256>>>(
        (const float*)po, (const float*)ml, (__half*)ao);

    // output projection (fp32 out)
    gemm_nt_f16<false><<<dim3(EMB / 128, SEQ / 128), 256, gemm_smem>>>(
        (const __half*)ao, (const __half*)wo, d_out, SEQ, EMB, EMB);
}

// round 16
// speedup vs baseline: 1.1958x; 1.0130x over previous
#include <cuda_runtime.h>
#include <cuda_fp16.h>
#include <cstdint>

// Problem constants
#define SEQ   4096
#define EMB   2048
#define NH    16
#define NKV   4
#define DHEAD 128
#define QKVD  3072   // packed q|k|v projection dim: 2048 + 512 + 512
#define NSPLIT 2     // split-KV factor in flash attention

// ---------------------------------------------------------------------------
// Scratch (device globals — no cudaMalloc allowed)
// ---------------------------------------------------------------------------
__device__ __half g_xh[SEQ * EMB];            // x fp16
__device__ __half g_wqkv[QKVD * EMB];         // packed [Wq;Wk;Wv] fp16
__device__ __half g_wo[EMB * EMB];            // Wo fp16
__device__ __half g_qkv[SEQ * QKVD];          // packed Q|K|V [4096,3072]
__device__ __half g_ao[SEQ * EMB];            // attention out (merged heads)
__device__ __half g_po[NSPLIT * NH * SEQ * DHEAD];  // unnormalized O partials fp16
__device__ float  g_ml[NSPLIT * NH * SEQ * 2];      // (m, l) per row per split

// ---------------------------------------------------------------------------
// Helpers
// ---------------------------------------------------------------------------
__device__ __forceinline__ unsigned smem_u32(const void* p) {
    return (unsigned)__cvta_generic_to_shared(p);
}

__device__ __forceinline__ void cp_async16(void* smem, const void* gmem) {
    asm volatile("cp.async.cg.shared.global [%0], [%1], 16;\n"
                 :: "r"(smem_u32(smem)), "l"(gmem));
}
__device__ __forceinline__ void cp_commit() {
    asm volatile("cp.async.commit_group;\n");
}
template <int N>
__device__ __forceinline__ void cp_wait() {
    asm volatile("cp.async.wait_group %0;\n" :: "n"(N));
}

__device__ __forceinline__ void ldm_x4(unsigned& r0, unsigned& r1,
                                       unsigned& r2, unsigned& r3, unsigned addr) {
    asm volatile("ldmatrix.sync.aligned.m8n8.x4.shared.b16 {%0,%1,%2,%3}, [%4];"
                 : "=r"(r0), "=r"(r1), "=r"(r2), "=r"(r3) : "r"(addr));
}
__device__ __forceinline__ void ldm_x4_t(unsigned& r0, unsigned& r1,
                                         unsigned& r2, unsigned& r3, unsigned addr) {
    asm volatile("ldmatrix.sync.aligned.m8n8.x4.trans.shared.b16 {%0,%1,%2,%3}, [%4];"
                 : "=r"(r0), "=r"(r1), "=r"(r2), "=r"(r3) : "r"(addr));
}
__device__ __forceinline__ void mma16816(float* c, const unsigned* a,
                                         unsigned b0, unsigned b1) {
    asm volatile(
        "mma.sync.aligned.m16n8k16.row.col.f32.f16.f16.f32 "
        "{%0,%1,%2,%3}, {%4,%5,%6,%7}, {%8,%9}, {%0,%1,%2,%3};"
        : "+f"(c[0]), "+f"(c[1]), "+f"(c[2]), "+f"(c[3])
        : "r"(a[0]), "r"(a[1]), "r"(a[2]), "r"(a[3]), "r"(b0), "r"(b1));
}

// ---------------------------------------------------------------------------
// Fused fp32 -> fp16 convert for all five inputs, 32B per thread.
// Region table in float4 units (all boundaries even, so a 2-unit pair
// never straddles regions):
//   x   : [0,        2097152)  -> g_xh
//   Wq  : [2097152,  3145728)  -> g_wqkv + 0
//   Wk  : [3145728,  3407872)  -> g_wqkv + 4194304
//   Wv  : [3407872,  3670016)  -> g_wqkv + 5242880
//   Wo  : [3670016,  4718592)  -> g_wo
// ---------------------------------------------------------------------------
__global__ void cvt_all(const float* __restrict__ x,  const float* __restrict__ wq,
                        const float* __restrict__ wk, const float* __restrict__ wv,
                        const float* __restrict__ wo,
                        __half* __restrict__ xh, __half* __restrict__ wqkv,
                        __half* __restrict__ woh)
{
    int u = (blockIdx.x * blockDim.x + threadIdx.x) * 2;
    const float* src; __half* dst; int off;
    if (u < 2097152)       { src = x;  dst = xh;             off = u; }
    else if (u < 3145728)  { src = wq; dst = wqkv;           off = u - 2097152; }
    else if (u < 3407872)  { src = wk; dst = wqkv + 4194304; off = u - 3145728; }
    else if (u < 3670016)  { src = wv; dst = wqkv + 5242880; off = u - 3407872; }
    else                   { src = wo; dst = woh;            off = u - 3670016; }
    float4 v0 = reinterpret_cast<const float4*>(src)[off];
    float4 v1 = reinterpret_cast<const float4*>(src)[off + 1];
    __half2 h[4];
    h[0] = __floats2half2_rn(v0.x, v0.y);
    h[1] = __floats2half2_rn(v0.z, v0.w);
    h[2] = __floats2half2_rn(v1.x, v1.y);
    h[3] = __floats2half2_rn(v1.z, v1.w);
    *reinterpret_cast<uint4*>(dst + (size_t)off * 4) = *reinterpret_cast<uint4*>(h);
}

// ---------------------------------------------------------------------------
// NT GEMM: C[M,N] = A[M,K] @ B[N,K]^T, fp16 in, fp32 accumulate.
// BM=128, BN=128, BK=32, 256 threads (8 warps: 4 in M x 2 in N).
// 4-stage cp.async pipeline, one __syncthreads per k-iteration.
// SMEM stride 40 halfs. Dynamic smem = 81920 B.
// ---------------------------------------------------------------------------
#define GSTG 5120   // 128*40 halfs per stage

template <bool OUT_HALF>
__global__ __launch_bounds__(256, 2) void gemm_nt_f16(
    const __half* __restrict__ A, const __half* __restrict__ B,
    void* __restrict__ Cp, int M, int N, int K)
{
    extern __shared__ __half gsm[];
    __half* As = gsm;
    __half* Bs = gsm + 4 * GSTG;

    const int tid = threadIdx.x;
    const int lane = tid & 31, wid = tid >> 5;
    const int wm = wid & 3, wn = wid >> 2;
    const int m0 = blockIdx.y * 128, n0 = blockIdx.x * 128;
    const int lr = lane & 7, sel = lane >> 3;

    const int nk = K >> 5;

    auto issue = [&](int it) {
        int s = it & 3;
        __half* as = As + s * GSTG;
        __half* bs = Bs + s * GSTG;
        int k0 = it * 32;
#pragma unroll
        for (int i = 0; i < 2; i++) {
            int v = tid + i * 256;
            int row = v >> 2, col = (v & 3) * 8;
            cp_async16(&as[row * 40 + col], A + (size_t)(m0 + row) * K + k0 + col);
            cp_async16(&bs[row * 40 + col], B + (size_t)(n0 + row) * K + k0 + col);
        }
    };

    float acc[2][8][4];
#pragma unroll
    for (int mt = 0; mt < 2; mt++)
#pragma unroll
        for (int nt = 0; nt < 8; nt++)
#pragma unroll
            for (int j = 0; j < 4; j++) acc[mt][nt][j] = 0.f;

    issue(0); cp_commit();
    issue(1); cp_commit();
    issue(2); cp_commit();

    for (int i = 0; i < nk; i++) {
        cp_wait<2>();
        __syncthreads();
        if (i + 3 < nk) issue(i + 3);
        cp_commit();

        int s = i & 3;
        const __half* as = As + s * GSTG;
        const __half* bs = Bs + s * GSTG;

#pragma unroll
        for (int ks = 0; ks < 32; ks += 16) {
            unsigned a[2][4];
#pragma unroll
            for (int mt = 0; mt < 2; mt++) {
                int row = wm * 32 + mt * 16 + lr + (sel & 1) * 8;
                int col = ks + (sel >> 1) * 8;
                ldm_x4(a[mt][0], a[mt][1], a[mt][2], a[mt][3],
                       smem_u32(&as[row * 40 + col]));
            }
#pragma unroll
            for (int np = 0; np < 4; np++) {
                unsigned b[4];
                int row = wn * 64 + np * 16 + lr + (sel >> 1) * 8;
                int col = ks + (sel & 1) * 8;
                ldm_x4(b[0], b[1], b[2], b[3], smem_u32(&bs[row * 40 + col]));
#pragma unroll
                for (int mt = 0; mt < 2; mt++) {
                    mma16816(acc[mt][2 * np], a[mt], b[0], b[1]);
                    mma16816(acc[mt][2 * np + 1], a[mt], b[2], b[3]);
                }
            }
        }
    }

    const int g = lane >> 2, t = lane & 3;
#pragma unroll
    for (int mt = 0; mt < 2; mt++) {
#pragma unroll
        for (int nt = 0; nt < 8; nt++) {
            int row = m0 + wm * 32 + mt * 16 + g;
            int col = n0 + wn * 64 + nt * 8 + t * 2;
            if (OUT_HALF) {
                __half* C = (__half*)Cp;
                *reinterpret_cast<__half2*>(C + (size_t)row * N + col) =
                    __floats2half2_rn(acc[mt][nt][0], acc[mt][nt][1]);
                *reinterpret_cast<__half2*>(C + (size_t)(row + 8) * N + col) =
                    __floats2half2_rn(acc[mt][nt][2], acc[mt][nt][3]);
            } else {
                float* C = (float*)Cp;
                *reinterpret_cast<float2*>(C + (size_t)row * N + col) =
                    make_float2(acc[mt][nt][0], acc[mt][nt][1]);
                *reinterpret_cast<float2*>(C + (size_t)(row + 8) * N + col) =
                    make_float2(acc[mt][nt][2], acc[mt][nt][3]);
            }
        }
    }
}

// ---------------------------------------------------------------------------
// Flash attention with split-KV. grid = (SEQ/128, NH, NSPLIT), 256 threads.
// Each CTA: 128 q-rows of one head over half the KV range (independent online
// softmax); writes UNnormalized fp16 O-partials + fp32 (m, l).
// Dynamic smem = (128 + 3*128) * 136 * 2 = 139264 B.
// ---------------------------------------------------------------------------
#define FSTG (128 * 136)  // one KV stage (K 64x136 + V 64x136) in halfs
#define KVHALF (SEQ / NSPLIT)

__global__ __launch_bounds__(256) void flash_attn(
    const __half* __restrict__ QKV, __half* __restrict__ PO, float* __restrict__ ML)
{
    extern __shared__ __half fsm[];
    __half* Qs  = fsm;            // 128*136
    __half* KVs = fsm + FSTG;     // 3 stages

    const int tid = threadIdx.x, lane = tid & 31, wid = tid >> 5;
    const int h = blockIdx.y;
    const int q0 = blockIdx.x * 128;
    const int sp = blockIdx.z;                      // KV split index
    const int kvh = h >> 2;                         // GQA repeat_interleave(4)
    const int lr = lane & 7, sel = lane >> 3;
    const int g = lane >> 2, t = lane & 3;

    const __half* qg = QKV + (size_t)q0 * QKVD + h * DHEAD;
    const __half* kg = QKV + 2048 + (size_t)kvh * DHEAD + (size_t)sp * KVHALF * QKVD;
    const __half* vg = QKV + 2560 + (size_t)kvh * DHEAD + (size_t)sp * KVHALF * QKVD;

    auto issueKV = [&](int it) {
        int s = it % 3;
        __half* ks = KVs + s * FSTG;
        __half* vs = ks + 64 * 136;
        int kv0 = it * 64;
#pragma unroll
        for (int i = 0; i < 4; i++) {
            int v = tid + i * 256;
            int row = v >> 4, col = (v & 15) * 8;
            cp_async16(&ks[row * 136 + col], kg + (size_t)(kv0 + row) * QKVD + col);
            cp_async16(&vs[row * 136 + col], vg + (size_t)(kv0 + row) * QKVD + col);
        }
    };

    // group 0: Q tile
#pragma unroll
    for (int i = 0; i < 8; i++) {
        int v = tid + i * 256;
        int row = v >> 4, col = (v & 15) * 8;
        cp_async16(&Qs[row * 136 + col], qg + (size_t)row * QKVD + col);
    }
    cp_commit();
    issueKV(0); cp_commit();
    issueKV(1); cp_commit();

    cp_wait<2>();
    __syncthreads();

    unsigned qf[8][4];
    {
        int row = wid * 16 + lr + (sel & 1) * 8;
#pragma unroll
        for (int kt = 0; kt < 8; kt++) {
            int col = kt * 16 + (sel >> 1) * 8;
            ldm_x4(qf[kt][0], qf[kt][1], qf[kt][2], qf[kt][3],
                   smem_u32(&Qs[row * 136 + col]));
        }
    }

    float oacc[16][4];
#pragma unroll
    for (int nt = 0; nt < 16; nt++)
#pragma unroll
        for (int j = 0; j < 4; j++) oacc[nt][j] = 0.f;

    float mrow0 = -1e30f, mrow1 = -1e30f;
    float lrow0 = 0.f, lrow1 = 0.f;
    const float scale = 0.1275174302f;   // (1/sqrt(128)) * log2(e)

    const int nkv = KVHALF / 64;
    for (int i = 0; i < nkv; i++) {
        cp_wait<1>();
        __syncthreads();
        if (i + 2 < nkv) issueKV(i + 2);
        cp_commit();

        int s = i % 3;
        const __half* Ks = KVs + s * FSTG;
        const __half* Vs = Ks + 64 * 136;

        // --- S = Q @ K^T  (16 x 64 per warp) ---
        float sacc[8][4];
#pragma unroll
        for (int nt = 0; nt < 8; nt++)
#pragma unroll
            for (int j = 0; j < 4; j++) sacc[nt][j] = 0.f;

#pragma unroll
        for (int kt = 0; kt < 8; kt++) {
#pragma unroll
            for (int np = 0; np < 4; np++) {
                unsigned b[4];
                int row = np * 16 + lr + (sel >> 1) * 8;
                int col = kt * 16 + (sel & 1) * 8;
                ldm_x4(b[0], b[1], b[2], b[3], smem_u32(&Ks[row * 136 + col]));
                mma16816(sacc[2 * np], qf[kt], b[0], b[1]);
                mma16816(sacc[2 * np + 1], qf[kt], b[2], b[3]);
            }
        }

        // --- online softmax (base-2 domain) ---
        float mnew0 = mrow0, mnew1 = mrow1;
#pragma unroll
        for (int nt = 0; nt < 8; nt++) {
#pragma unroll
            for (int j = 0; j < 4; j++) sacc[nt][j] *= scale;
            mnew0 = fmaxf(mnew0, fmaxf(sacc[nt][0], sacc[nt][1]));
            mnew1 = fmaxf(mnew1, fmaxf(sacc[nt][2], sacc[nt][3]));
        }
        mnew0 = fmaxf(mnew0, __shfl_xor_sync(0xffffffffu, mnew0, 1));
        mnew0 = fmaxf(mnew0, __shfl_xor_sync(0xffffffffu, mnew0, 2));
        mnew1 = fmaxf(mnew1, __shfl_xor_sync(0xffffffffu, mnew1, 1));
        mnew1 = fmaxf(mnew1, __shfl_xor_sync(0xffffffffu, mnew1, 2));

        float alpha0 = exp2f(mrow0 - mnew0);
        float alpha1 = exp2f(mrow1 - mnew1);
        float rsum0 = 0.f, rsum1 = 0.f;

        unsigned ph[4][4];
#pragma unroll
        for (int nt = 0; nt < 8; nt++) {
            float p0 = exp2f(sacc[nt][0] - mnew0);
            float p1 = exp2f(sacc[nt][1] - mnew0);
            float p2 = exp2f(sacc[nt][2] - mnew1);
            float p3 = exp2f(sacc[nt][3] - mnew1);
            rsum0 += p0 + p1;
            rsum1 += p2 + p3;
            __half2 h01 = __floats2half2_rn(p0, p1);
            __half2 h23 = __floats2half2_rn(p2, p3);
            int kt = nt >> 1;
            if ((nt & 1) == 0) {
                ph[kt][0] = *reinterpret_cast<unsigned*>(&h01);
                ph[kt][1] = *reinterpret_cast<unsigned*>(&h23);
            } else {
                ph[kt][2] = *reinterpret_cast<unsigned*>(&h01);
                ph[kt][3] = *reinterpret_cast<unsigned*>(&h23);
            }
        }
        rsum0 += __shfl_xor_sync(0xffffffffu, rsum0, 1);
        rsum0 += __shfl_xor_sync(0xffffffffu, rsum0, 2);
        rsum1 += __shfl_xor_sync(0xffffffffu, rsum1, 1);
        rsum1 += __shfl_xor_sync(0xffffffffu, rsum1, 2);

        lrow0 = lrow0 * alpha0 + rsum0;
        lrow1 = lrow1 * alpha1 + rsum1;
        mrow0 = mnew0;
        mrow1 = mnew1;

#pragma unroll
        for (int nt = 0; nt < 16; nt++) {
            oacc[nt][0] *= alpha0; oacc[nt][1] *= alpha0;
            oacc[nt][2] *= alpha1; oacc[nt][3] *= alpha1;
        }

        // --- O += P @ V ---
#pragma unroll
        for (int kt = 0; kt < 4; kt++) {
#pragma unroll
            for (int np = 0; np < 8; np++) {
                unsigned b[4];
                int row = kt * 16 + lr + (sel & 1) * 8;
                int col = np * 16 + (sel >> 1) * 8;
                ldm_x4_t(b[0], b[1], b[2], b[3], smem_u32(&Vs[row * 136 + col]));
                mma16816(oacc[2 * np], ph[kt], b[0], b[1]);
                mma16816(oacc[2 * np + 1], ph[kt], b[2], b[3]);
            }
        }
    }

    // --- epilogue: store UNnormalized fp16 partials + fp32 (m, l) per row ---
    const size_t rowbase = ((size_t)(sp * NH + h) * SEQ + q0 + wid * 16);
    __half* pg = PO + rowbase * DHEAD;
#pragma unroll
    for (int nt = 0; nt < 16; nt++) {
        int col = nt * 8 + t * 2;
        *reinterpret_cast<__half2*>(pg + (size_t)g * DHEAD + col) =
            __floats2half2_rn(oacc[nt][0], oacc[nt][1]);
        *reinterpret_cast<__half2*>(pg + (size_t)(g + 8) * DHEAD + col) =
            __floats2half2_rn(oacc[nt][2], oacc[nt][3]);
    }
    if (t == 0) {
        ML[(rowbase + g) * 2 + 0] = mrow0;
        ML[(rowbase + g) * 2 + 1] = lrow0;
        ML[(rowbase + g + 8) * 2 + 0] = mrow1;
        ML[(rowbase + g + 8) * 2 + 1] = lrow1;
    }
}

// ---------------------------------------------------------------------------
// Combine the NSPLIT=2 KV splits: O = (O0*w0 + O1*w1) / (l0*w0 + l1*w1),
// w_i = 2^(m_i - max(m)). 8 halfs (16B) per thread, fp16 partial inputs.
// threads = SEQ*NH*(DHEAD/8) = 1,048,576 -> 4096 CTAs x 256.
// ---------------------------------------------------------------------------
__global__ void combine_split(const __half* __restrict__ po,
                              const float* __restrict__ ml,
                              __half* __restrict__ ao)
{
    int idx = blockIdx.x * blockDim.x + threadIdx.x;
    int d8 = idx & 15;               // 16 chunks of 8 halfs per row
    int qh = idx >> 4;
    int h = qh & 15;
    int q = qh >> 4;

    size_t rb = (size_t)h * SEQ + q;
    const size_t SML = (size_t)NH * SEQ * 2;        // split stride in ml
    const size_t SPO = (size_t)NH * SEQ * DHEAD;    // split stride in po

    float m0 = ml[rb * 2 + 0], l0 = ml[rb * 2 + 1];
    float m1 = ml[SML + rb * 2 + 0], l1 = ml[SML + rb * 2 + 1];
    float mx = fmaxf(m0, m1);
    float w0 = exp2f(m0 - mx), w1 = exp2f(m1 - mx);
    float inv = 1.f / (l0 * w0 + l1 * w1);
    w0 *= inv; w1 *= inv;

    size_t pb = rb * DHEAD + d8 * 8;
    uint4 a4 = *reinterpret_cast<const uint4*>(po + pb);
    uint4 b4 = *reinterpret_cast<const uint4*>(po + SPO + pb);
    const __half2* ah = reinterpret_cast<const __half2*>(&a4);
    const __half2* bh = reinterpret_cast<const __half2*>(&b4);

    __half2 out[4];
#pragma unroll
    for (int j = 0; j < 4; j++) {
        float2 fa = __half22float2(ah[j]);
        float2 fb = __half22float2(bh[j]);
        out[j] = __floats2half2_rn(fa.x * w0 + fb.x * w1, fa.y * w0 + fb.y * w1);
    }
    *reinterpret_cast<uint4*>(ao + (size_t)q * EMB + h * DHEAD + d8 * 8) =
        *reinterpret_cast<uint4*>(out);
}

// ---------------------------------------------------------------------------
// kernel_launch
// ---------------------------------------------------------------------------
extern "C" void kernel_launch(void* const* d_in, const int* in_sizes, int n_in,
                              void* d_out, int out_size) {
    (void)in_sizes; (void)n_in; (void)out_size;
    const float* x  = (const float*)d_in[0];
    const float* Wq = (const float*)d_in[1];
    const float* Wk = (const float*)d_in[2];
    const float* Wv = (const float*)d_in[3];
    const float* Wo = (const float*)d_in[4];

    void *xh, *wqkv, *wo, *qkv, *ao, *po, *ml;
    cudaGetSymbolAddress(&xh,   g_xh);
    cudaGetSymbolAddress(&wqkv, g_wqkv);
    cudaGetSymbolAddress(&wo,   g_wo);
    cudaGetSymbolAddress(&qkv,  g_qkv);
    cudaGetSymbolAddress(&ao,   g_ao);
    cudaGetSymbolAddress(&po,   g_po);
    cudaGetSymbolAddress(&ml,   g_ml);

    const int gemm_smem  = 2 * 4 * GSTG * (int)sizeof(__half);   // 81920
    const int flash_smem = 4 * FSTG * (int)sizeof(__half);       // 139264
    cudaFuncSetAttribute(gemm_nt_f16<true>,
                         cudaFuncAttributeMaxDynamicSharedMemorySize, gemm_smem);
    cudaFuncSetAttribute(gemm_nt_f16<false>,
                         cudaFuncAttributeMaxDynamicSharedMemorySize, gemm_smem);
    cudaFuncSetAttribute(flash_attn,
                         cudaFuncAttributeMaxDynamicSharedMemorySize, flash_smem);

    // fused fp32 -> fp16 converts (one launch, 32B per thread)
    cvt_all<<<9216, 256>>>(x, Wq, Wk, Wv, Wo,
                           (__half*)xh, (__half*)wqkv, (__half*)wo);

    // fused QKV projection: [4096,3072] = X @ [Wq;Wk;Wv]^T
    gemm_nt_f16<true><<<dim3(QKVD / 128, SEQ / 128), 256, gemm_smem>>>(
        (const __half*)xh, (const __half*)wqkv, qkv, SEQ, QKVD, EMB);

    // attention (split-KV x2), then combine
    flash_attn<<<dim3(SEQ / 128, NH, NSPLIT), 256, flash_smem>>>(
        (const __half*)qkv, (__half*)po, (float*)ml);
    combine_split<<<(SEQ * NH * (DHEAD / 8)) / 256, 256>>>(
        (const __half*)po, (const float*)ml, (__half*)ao);

    // output projection (fp32 out)
    gemm_nt_f16<false><<<dim3(EMB / 128, SEQ / 128), 256, gemm_smem>>>(
        (const __half*)ao, (const __half*)wo, d_out, SEQ, EMB, EMB);
}